// round 1
// baseline (speedup 1.0000x reference)
#include <cuda_runtime.h>
#include <cstring>

// ---------------------------------------------------------------------------
// HyperEConv: two message-passing steps.
//   xv = x@Wx1^T+bx1 ; wv = w@Ww1^T+bw1
//   aggr_x[vidx] += wv[eidx]           (segment sum over 800K edges)
//   x_new = xv * (1 + aggr_x)
//   xe = x_new@Wx2^T+bx2 ; we = w@Ww2^T+bw2
//   aggr_w[eidx] += xe[vidx]
//   w_new = we * (1 + aggr_w)
// Output: [w_new (N_W*128) | x_new (N_X*128)]  float32
// ---------------------------------------------------------------------------

#define MAX_NX 100000
#define MAX_NW 25000
#define D 128

// scratch (device globals; no allocation allowed in kernel_launch)
__device__ float g_xv  [MAX_NX * D];
__device__ float g_wv  [MAX_NW * D];
__device__ float g_aggx[MAX_NX * D];
__device__ float g_xe  [MAX_NX * D];
__device__ float g_we  [MAX_NW * D];
__device__ float g_aggw[MAX_NW * D];

// packed f32x2 FMA (2x fp32 FMA throughput; only reachable via PTX)
__device__ __forceinline__ float2 ffma2(float2 a, float2 b, float2 c) {
    unsigned long long au, bu, cu, du;
    memcpy(&au, &a, 8); memcpy(&bu, &b, 8); memcpy(&cu, &c, 8);
    asm("fma.rn.f32x2 %0, %1, %2, %3;" : "=l"(du) : "l"(au), "l"(bu), "l"(cu));
    float2 d; memcpy(&d, &du, 8);
    return d;
}

// ---------------------------------------------------------------------------
// GEMM: C[M,128] = A[M,128] @ W^T + bias,  W is [128,128] row-major (out,in)
// Block: 256 threads, tile 128 rows x 128 cols, K=128 (all of it).
// Smem: A and W both stored k-major (transposed) so the inner loop does
// conflict-free LDS. Each thread computes 8 rows x 8 cols as 4 row-pairs x 8
// cols of f32x2 accumulators (row pair packed -> fma.rn.f32x2).
// ---------------------------------------------------------------------------
extern __shared__ float smem_dyn[];

__global__ void __launch_bounds__(256, 1)
gemm128_kernel(const float* __restrict__ A, const float* __restrict__ W,
               const float* __restrict__ bias, float* __restrict__ C, int M)
{
    float* Ast = smem_dyn;             // [128][128], Ast[k][row]
    float* Wt  = smem_dyn + 128 * 128; // [128][128], Wt[k][col]

    const int t  = threadIdx.x;
    const int tx = t & 15;   // 0..15 -> col group
    const int ty = t >> 4;   // 0..15 -> row group
    const int rowBase = blockIdx.x * 128;

    // --- load A tile and W (transposed into smem) ---
    {
        const int r  = t >> 1;          // 0..127
        const int kh = (t & 1) * 64;    // k half
        const int grow = rowBase + r;
        const bool valid = grow < M;
        const float4* Ag = (const float4*)(A + (size_t)grow * D + kh);
        const float4* Wg = (const float4*)(W + (size_t)r * D + kh);
        #pragma unroll
        for (int q = 0; q < 16; q++) {
            float4 va = valid ? Ag[q] : make_float4(0.f, 0.f, 0.f, 0.f);
            int k0 = kh + q * 4;
            Ast[(k0 + 0) * 128 + r] = va.x;
            Ast[(k0 + 1) * 128 + r] = va.y;
            Ast[(k0 + 2) * 128 + r] = va.z;
            Ast[(k0 + 3) * 128 + r] = va.w;
            float4 vw = Wg[q];
            Wt[(k0 + 0) * 128 + r] = vw.x;
            Wt[(k0 + 1) * 128 + r] = vw.y;
            Wt[(k0 + 2) * 128 + r] = vw.z;
            Wt[(k0 + 3) * 128 + r] = vw.w;
        }
    }
    __syncthreads();

    float2 acc[4][8];
    #pragma unroll
    for (int i = 0; i < 4; i++)
        #pragma unroll
        for (int p = 0; p < 8; p++) acc[i][p] = make_float2(0.f, 0.f);

    #pragma unroll 4
    for (int k = 0; k < 128; k++) {
        float2 a2[4];
        #pragma unroll
        for (int i = 0; i < 4; i++)
            a2[i] = *(const float2*)&Ast[k * 128 + ty * 8 + 2 * i];
        #pragma unroll
        for (int p = 0; p < 8; p++) {
            float w = Wt[k * 128 + tx + 16 * p];
            float2 w2 = make_float2(w, w);
            #pragma unroll
            for (int i = 0; i < 4; i++)
                acc[i][p] = ffma2(a2[i], w2, acc[i][p]);
        }
    }

    // --- epilogue: add bias, store ---
    float b[8];
    #pragma unroll
    for (int p = 0; p < 8; p++) b[p] = bias[tx + 16 * p];

    #pragma unroll
    for (int i = 0; i < 4; i++) {
        int r0 = rowBase + ty * 8 + 2 * i;
        #pragma unroll
        for (int p = 0; p < 8; p++) {
            int col = tx + 16 * p;
            if (r0 < M)     C[(size_t)r0 * D + col]       = acc[i][p].x + b[p];
            if (r0 + 1 < M) C[(size_t)(r0 + 1) * D + col] = acc[i][p].y + b[p];
        }
    }
}

// ---------------------------------------------------------------------------
// Scatter-add: dst[dstIdx[e]] += src[srcIdx[e]]  (rows of 128 floats)
// One warp per edge: each lane handles one float4 (32 lanes * 4 = 128).
// Uses red.global.add.v4.f32 (no-return reduction; L2-side atomic ALU).
// ---------------------------------------------------------------------------
__global__ void scatter_add_kernel(const float* __restrict__ src,
                                   const int* __restrict__ srcIdx,
                                   const int* __restrict__ dstIdx,
                                   float* __restrict__ dst, int E)
{
    const int total = E * 32;   // one item = one float4
    const int stride = gridDim.x * blockDim.x;
    for (int i = blockIdx.x * blockDim.x + threadIdx.x; i < total; i += stride) {
        int e = i >> 5;
        int j = (i & 31) << 2;
        int s = srcIdx[e];
        int d = dstIdx[e];
        float4 v = *(const float4*)(src + (size_t)s * D + j);
        float* p = dst + (size_t)d * D + j;
        asm volatile("red.global.add.v4.f32 [%0], {%1,%2,%3,%4};"
                     :: "l"(p), "f"(v.x), "f"(v.y), "f"(v.z), "f"(v.w)
                     : "memory");
    }
}

// ---------------------------------------------------------------------------
// out = lin * (1 + aggr)   (vectorized)
// ---------------------------------------------------------------------------
__global__ void update_kernel(const float* __restrict__ lin,
                              const float* __restrict__ aggr,
                              float* __restrict__ out, int n4)
{
    const int stride = gridDim.x * blockDim.x;
    for (int i = blockIdx.x * blockDim.x + threadIdx.x; i < n4; i += stride) {
        float4 l = ((const float4*)lin)[i];
        float4 a = ((const float4*)aggr)[i];
        float4 o;
        o.x = fmaf(a.x, l.x, l.x);
        o.y = fmaf(a.y, l.y, l.y);
        o.z = fmaf(a.z, l.z, l.z);
        o.w = fmaf(a.w, l.w, l.w);
        ((float4*)out)[i] = o;
    }
}

extern "C" void kernel_launch(void* const* d_in, const int* in_sizes, int n_in,
                              void* d_out, int out_size)
{
    const float* x   = (const float*)d_in[0];
    const float* w   = (const float*)d_in[1];
    const float* Wx1 = (const float*)d_in[2];
    const float* bx1 = (const float*)d_in[3];
    const float* Ww1 = (const float*)d_in[4];
    const float* bw1 = (const float*)d_in[5];
    const float* Wx2 = (const float*)d_in[6];
    const float* bx2 = (const float*)d_in[7];
    const float* Ww2 = (const float*)d_in[8];
    const float* bw2 = (const float*)d_in[9];
    const int*   h   = (const int*)d_in[10];

    const int N_X = in_sizes[0] / D;
    const int N_W = in_sizes[1] / D;
    const int E   = in_sizes[10] / 2;
    const int* vidx = h;
    const int* eidx = h + E;

    float* out_w = (float*)d_out;
    float* out_x = (float*)d_out + (size_t)N_W * D;

    float *p_xv, *p_wv, *p_aggx, *p_xe, *p_we, *p_aggw;
    cudaGetSymbolAddress((void**)&p_xv,   g_xv);
    cudaGetSymbolAddress((void**)&p_wv,   g_wv);
    cudaGetSymbolAddress((void**)&p_aggx, g_aggx);
    cudaGetSymbolAddress((void**)&p_xe,   g_xe);
    cudaGetSymbolAddress((void**)&p_we,   g_we);
    cudaGetSymbolAddress((void**)&p_aggw, g_aggw);

    const int SMEM = 2 * 128 * 128 * (int)sizeof(float); // 128 KB
    cudaFuncSetAttribute(gemm128_kernel,
                         cudaFuncAttributeMaxDynamicSharedMemorySize, SMEM);

    const int gx = (N_X + 127) / 128;
    const int gw = (N_W + 127) / 128;

    // ---- step 1: MPToVertex ----
    gemm128_kernel<<<gx, 256, SMEM>>>(x, Wx1, bx1, p_xv, N_X);
    gemm128_kernel<<<gw, 256, SMEM>>>(w, Ww1, bw1, p_wv, N_W);
    cudaMemsetAsync(p_aggx, 0, (size_t)N_X * D * sizeof(float));
    scatter_add_kernel<<<2048, 256>>>(p_wv, eidx, vidx, p_aggx, E);
    update_kernel<<<2048, 256>>>(p_xv, p_aggx, out_x, N_X * D / 4);

    // ---- step 2: MPToEdge ----
    gemm128_kernel<<<gx, 256, SMEM>>>(out_x, Wx2, bx2, p_xe, N_X);
    gemm128_kernel<<<gw, 256, SMEM>>>(w, Ww2, bw2, p_we, N_W);
    cudaMemsetAsync(p_aggw, 0, (size_t)N_W * D * sizeof(float));
    scatter_add_kernel<<<2048, 256>>>(p_xe, vidx, eidx, p_aggw, E);
    update_kernel<<<2048, 256>>>(p_we, p_aggw, out_w, N_W * D / 4);
}

// round 2
// speedup vs baseline: 1.4391x; 1.4391x over previous
#include <cuda_runtime.h>
#include <cstring>

// ---------------------------------------------------------------------------
// HyperEConv, restructured:
//   xv = x@Wx1^T+bx1 ; wv = w@Ww1^T+bw1
//   x_new = xv * (1 + segsum_v(wv[eidx]))            (CSR gather-reduce, fused)
//   s     = segsum_e(x_new[vidx])                    (CSR gather-reduce)
//   aggr_w = s@Wx2^T + deg_w*bx2                     (linearity of GEMM)
//   w_new = (w@Ww2^T + bw2) * (1 + aggr_w)           (fused GEMM epilogue)
// Output: [w_new (N_W*128) | x_new (N_X*128)]  float32
// ---------------------------------------------------------------------------

#define MAX_NX 100000
#define MAX_NW 25000
#define MAX_E  800000
#define D 128

// scratch (device globals; no allocation allowed)
__device__ float g_xv  [MAX_NX * D];
__device__ float g_wv  [MAX_NW * D];
__device__ float g_s   [MAX_NW * D];
__device__ float g_aggw[MAX_NW * D];

__device__ int g_cntx[MAX_NX];
__device__ int g_offx[MAX_NX + 1];
__device__ int g_curx[MAX_NX];
__device__ int g_cntw[MAX_NW];
__device__ int g_offw[MAX_NW + 1];
__device__ int g_curw[MAX_NW];
__device__ int g_srcx[MAX_E];
__device__ int g_srcw[MAX_E];
__device__ int g_bsumx[128];
__device__ int g_bsumw[128];

// packed f32x2 FMA (2x fp32 FMA throughput; only reachable via PTX)
__device__ __forceinline__ float2 ffma2(float2 a, float2 b, float2 c) {
    unsigned long long au, bu, cu, du;
    memcpy(&au, &a, 8); memcpy(&bu, &b, 8); memcpy(&cu, &c, 8);
    asm("fma.rn.f32x2 %0, %1, %2, %3;" : "=l"(du) : "l"(au), "l"(bu), "l"(cu));
    float2 d; memcpy(&d, &du, 8);
    return d;
}

// ---------------------------------------------------------------------------
// GEMM: C[M,128] = A[M,128] @ W^T + scale*bias, optionally fused
//   scale = deg[row] if deg != nullptr else 1
//   if mul != nullptr: C = C * (1 + mul)   (elementwise)
// ---------------------------------------------------------------------------
extern __shared__ float smem_dyn[];

__global__ void __launch_bounds__(256, 1)
gemm128_kernel(const float* __restrict__ A, const float* __restrict__ W,
               const float* __restrict__ bias, float* __restrict__ C, int M,
               const int* __restrict__ deg, const float* __restrict__ mul)
{
    float* Ast = smem_dyn;             // [128][128], Ast[k][row]
    float* Wt  = smem_dyn + 128 * 128; // [128][128], Wt[k][col]

    const int t  = threadIdx.x;
    const int tx = t & 15;
    const int ty = t >> 4;
    const int rowBase = blockIdx.x * 128;

    {
        const int r  = t >> 1;
        const int kh = (t & 1) * 64;
        const int grow = rowBase + r;
        const bool valid = grow < M;
        const float4* Ag = (const float4*)(A + (size_t)grow * D + kh);
        const float4* Wg = (const float4*)(W + (size_t)r * D + kh);
        #pragma unroll
        for (int q = 0; q < 16; q++) {
            float4 va = valid ? Ag[q] : make_float4(0.f, 0.f, 0.f, 0.f);
            int k0 = kh + q * 4;
            Ast[(k0 + 0) * 128 + r] = va.x;
            Ast[(k0 + 1) * 128 + r] = va.y;
            Ast[(k0 + 2) * 128 + r] = va.z;
            Ast[(k0 + 3) * 128 + r] = va.w;
            float4 vw = Wg[q];
            Wt[(k0 + 0) * 128 + r] = vw.x;
            Wt[(k0 + 1) * 128 + r] = vw.y;
            Wt[(k0 + 2) * 128 + r] = vw.z;
            Wt[(k0 + 3) * 128 + r] = vw.w;
        }
    }
    __syncthreads();

    float2 acc[4][8];
    #pragma unroll
    for (int i = 0; i < 4; i++)
        #pragma unroll
        for (int p = 0; p < 8; p++) acc[i][p] = make_float2(0.f, 0.f);

    #pragma unroll 4
    for (int k = 0; k < 128; k++) {
        float2 a2[4];
        #pragma unroll
        for (int i = 0; i < 4; i++)
            a2[i] = *(const float2*)&Ast[k * 128 + ty * 8 + 2 * i];
        #pragma unroll
        for (int p = 0; p < 8; p++) {
            float wv_ = Wt[k * 128 + tx + 16 * p];
            float2 w2 = make_float2(wv_, wv_);
            #pragma unroll
            for (int i = 0; i < 4; i++)
                acc[i][p] = ffma2(a2[i], w2, acc[i][p]);
        }
    }

    float b[8];
    #pragma unroll
    for (int p = 0; p < 8; p++) b[p] = bias[tx + 16 * p];

    const bool hasMul = (mul != nullptr);

    #pragma unroll
    for (int i = 0; i < 4; i++) {
        int r0 = rowBase + ty * 8 + 2 * i;
        float d0 = 1.f, d1 = 1.f;
        if (deg != nullptr) {
            if (r0 < M)     d0 = (float)deg[r0];
            if (r0 + 1 < M) d1 = (float)deg[r0 + 1];
        }
        #pragma unroll
        for (int p = 0; p < 8; p++) {
            int col = tx + 16 * p;
            if (r0 < M) {
                float v = acc[i][p].x + b[p] * d0;
                if (hasMul) { float m = mul[(size_t)r0 * D + col]; v = fmaf(v, m, v); }
                C[(size_t)r0 * D + col] = v;
            }
            if (r0 + 1 < M) {
                float v = acc[i][p].y + b[p] * d1;
                if (hasMul) { float m = mul[(size_t)(r0 + 1) * D + col]; v = fmaf(v, m, v); }
                C[(size_t)(r0 + 1) * D + col] = v;
            }
        }
    }
}

// ---------------------------------------------------------------------------
// CSR construction: histogram -> block scan -> top scan -> add + cursor -> place
// ---------------------------------------------------------------------------
__global__ void hist_kernel(const int* __restrict__ vidx, const int* __restrict__ eidx,
                            int* cntx, int* cntw, int E)
{
    const int stride = gridDim.x * blockDim.x;
    for (int e = blockIdx.x * blockDim.x + threadIdx.x; e < E; e += stride) {
        atomicAdd(&cntx[vidx[e]], 1);
        atomicAdd(&cntw[eidx[e]], 1);
    }
}

__global__ void __launch_bounds__(1024)
scan_block_kernel(const int* __restrict__ cnt, int* __restrict__ offs,
                  int* __restrict__ bsum, int n)
{
    __shared__ int sm[2][1024];
    const int t = threadIdx.x;
    const int i = blockIdx.x * 1024 + t;
    int v = (i < n) ? cnt[i] : 0;
    int cur = 0;
    sm[0][t] = v;
    __syncthreads();
    #pragma unroll
    for (int dstep = 1; dstep < 1024; dstep <<= 1) {
        int x = sm[cur][t];
        if (t >= dstep) x += sm[cur][t - dstep];
        sm[1 - cur][t] = x;
        cur ^= 1;
        __syncthreads();
    }
    int inc = sm[cur][t];
    if (i < n) offs[i] = inc - v;               // exclusive within block
    if (t == 1023) bsum[blockIdx.x] = inc;      // block total
}

__global__ void scan_tops_kernel(int* bsum, int nb)
{
    if (threadIdx.x == 0 && blockIdx.x == 0) {
        int run = 0;
        for (int i = 0; i < nb; i++) { int c = bsum[i]; bsum[i] = run; run += c; }
    }
}

__global__ void scan_add_kernel(int* offs, int* cursor, const int* __restrict__ bsum,
                                int n, int total)
{
    int i = blockIdx.x * blockDim.x + threadIdx.x;
    if (i == 0) offs[n] = total;
    if (i < n) {
        int o = offs[i] + bsum[i >> 10];
        offs[i] = o;
        cursor[i] = o;
    }
}

__global__ void place_kernel(const int* __restrict__ vidx, const int* __restrict__ eidx,
                             int* curx, int* curw, int* __restrict__ srcx,
                             int* __restrict__ srcw, int E)
{
    const int stride = gridDim.x * blockDim.x;
    for (int e = blockIdx.x * blockDim.x + threadIdx.x; e < E; e += stride) {
        int v = vidx[e], hw = eidx[e];
        int p1 = atomicAdd(&curx[v], 1);
        srcx[p1] = hw;
        int p2 = atomicAdd(&curw[hw], 1);
        srcw[p2] = v;
    }
}

// ---------------------------------------------------------------------------
// Segment gather-reduce: one warp per segment, lane = float4 column chunk.
//   acc = sum over k in [offs[seg], offs[seg+1]) of src[lst[k]]
//   out = lin ? lin*(1+acc) : acc
// ---------------------------------------------------------------------------
__global__ void seg_reduce_kernel(const int* __restrict__ offs, const int* __restrict__ lst,
                                  const float* __restrict__ src, const float* __restrict__ lin,
                                  float* __restrict__ out, int N)
{
    const int warp = (blockIdx.x * blockDim.x + threadIdx.x) >> 5;
    const int lane = threadIdx.x & 31;
    if (warp >= N) return;
    int k   = offs[warp];
    const int end = offs[warp + 1];
    float4 acc = make_float4(0.f, 0.f, 0.f, 0.f);
    // 2-deep software pipeline for MLP
    for (; k + 1 < end; k += 2) {
        int s0 = __ldg(&lst[k]);
        int s1 = __ldg(&lst[k + 1]);
        float4 v0 = *(const float4*)(src + (size_t)s0 * D + lane * 4);
        float4 v1 = *(const float4*)(src + (size_t)s1 * D + lane * 4);
        acc.x += v0.x + v1.x; acc.y += v0.y + v1.y;
        acc.z += v0.z + v1.z; acc.w += v0.w + v1.w;
    }
    if (k < end) {
        int s0 = __ldg(&lst[k]);
        float4 v0 = *(const float4*)(src + (size_t)s0 * D + lane * 4);
        acc.x += v0.x; acc.y += v0.y; acc.z += v0.z; acc.w += v0.w;
    }
    float4 o;
    if (lin != nullptr) {
        float4 l = *(const float4*)(lin + (size_t)warp * D + lane * 4);
        o.x = fmaf(acc.x, l.x, l.x);
        o.y = fmaf(acc.y, l.y, l.y);
        o.z = fmaf(acc.z, l.z, l.z);
        o.w = fmaf(acc.w, l.w, l.w);
    } else {
        o = acc;
    }
    *(float4*)(out + (size_t)warp * D + lane * 4) = o;
}

extern "C" void kernel_launch(void* const* d_in, const int* in_sizes, int n_in,
                              void* d_out, int out_size)
{
    const float* x   = (const float*)d_in[0];
    const float* w   = (const float*)d_in[1];
    const float* Wx1 = (const float*)d_in[2];
    const float* bx1 = (const float*)d_in[3];
    const float* Ww1 = (const float*)d_in[4];
    const float* bw1 = (const float*)d_in[5];
    const float* Wx2 = (const float*)d_in[6];
    const float* bx2 = (const float*)d_in[7];
    const float* Ww2 = (const float*)d_in[8];
    const float* bw2 = (const float*)d_in[9];
    const int*   h   = (const int*)d_in[10];

    const int N_X = in_sizes[0] / D;
    const int N_W = in_sizes[1] / D;
    const int E   = in_sizes[10] / 2;
    const int* vidx = h;
    const int* eidx = h + E;

    float* out_w = (float*)d_out;
    float* out_x = (float*)d_out + (size_t)N_W * D;

    float *p_xv, *p_wv, *p_s, *p_aggw;
    int *p_cntx, *p_offx, *p_curx, *p_cntw, *p_offw, *p_curw;
    int *p_srcx, *p_srcw, *p_bsumx, *p_bsumw;
    cudaGetSymbolAddress((void**)&p_xv,    g_xv);
    cudaGetSymbolAddress((void**)&p_wv,    g_wv);
    cudaGetSymbolAddress((void**)&p_s,     g_s);
    cudaGetSymbolAddress((void**)&p_aggw,  g_aggw);
    cudaGetSymbolAddress((void**)&p_cntx,  g_cntx);
    cudaGetSymbolAddress((void**)&p_offx,  g_offx);
    cudaGetSymbolAddress((void**)&p_curx,  g_curx);
    cudaGetSymbolAddress((void**)&p_cntw,  g_cntw);
    cudaGetSymbolAddress((void**)&p_offw,  g_offw);
    cudaGetSymbolAddress((void**)&p_curw,  g_curw);
    cudaGetSymbolAddress((void**)&p_srcx,  g_srcx);
    cudaGetSymbolAddress((void**)&p_srcw,  g_srcw);
    cudaGetSymbolAddress((void**)&p_bsumx, g_bsumx);
    cudaGetSymbolAddress((void**)&p_bsumw, g_bsumw);

    const int SMEM = 2 * 128 * 128 * (int)sizeof(float); // 128 KB
    cudaFuncSetAttribute(gemm128_kernel,
                         cudaFuncAttributeMaxDynamicSharedMemorySize, SMEM);

    const int gx = (N_X + 127) / 128;
    const int gw = (N_W + 127) / 128;
    const int nbx = (N_X + 1023) / 1024;
    const int nbw = (N_W + 1023) / 1024;

    // ---- GEMMs that don't depend on the graph structure ----
    gemm128_kernel<<<gx, 256, SMEM>>>(x, Wx1, bx1, p_xv, N_X, nullptr, nullptr);
    gemm128_kernel<<<gw, 256, SMEM>>>(w, Ww1, bw1, p_wv, N_W, nullptr, nullptr);

    // ---- CSR construction (both directions in one pass) ----
    cudaMemsetAsync(p_cntx, 0, (size_t)N_X * sizeof(int));
    cudaMemsetAsync(p_cntw, 0, (size_t)N_W * sizeof(int));
    hist_kernel<<<1024, 256>>>(vidx, eidx, p_cntx, p_cntw, E);
    scan_block_kernel<<<nbx, 1024>>>(p_cntx, p_offx, p_bsumx, N_X);
    scan_tops_kernel<<<1, 32>>>(p_bsumx, nbx);
    scan_add_kernel<<<(N_X + 255) / 256, 256>>>(p_offx, p_curx, p_bsumx, N_X, E);
    scan_block_kernel<<<nbw, 1024>>>(p_cntw, p_offw, p_bsumw, N_W);
    scan_tops_kernel<<<1, 32>>>(p_bsumw, nbw);
    scan_add_kernel<<<(N_W + 255) / 256, 256>>>(p_offw, p_curw, p_bsumw, N_W, E);
    place_kernel<<<1024, 256>>>(vidx, eidx, p_curx, p_curw, p_srcx, p_srcw, E);

    // ---- phase 1: x_new = xv * (1 + segsum_v(wv)) ----
    seg_reduce_kernel<<<(N_X + 7) / 8, 256>>>(p_offx, p_srcx, p_wv, p_xv, out_x, N_X);

    // ---- phase 2: s = segsum_e(x_new); aggr_w = s@Wx2^T + deg*bx2;
    //               w_new = (w@Ww2^T + bw2)*(1+aggr_w) ----
    seg_reduce_kernel<<<(N_W + 7) / 8, 256>>>(p_offw, p_srcw, out_x, nullptr, p_s, N_W);
    gemm128_kernel<<<gw, 256, SMEM>>>(p_s, Wx2, bx2, p_aggw, N_W, p_cntw, nullptr);
    gemm128_kernel<<<gw, 256, SMEM>>>(w, Ww2, bw2, out_w, N_W, nullptr, p_aggw);
}

// round 3
// speedup vs baseline: 1.6803x; 1.1676x over previous
#include <cuda_runtime.h>
#include <cstring>

// ---------------------------------------------------------------------------
// HyperEConv:
//   xv = x@Wx1^T+bx1 ; wv = w@Ww1^T+bw1 ; we = w@Ww2^T+bw2   (stream A)
//   CSR-x / CSR-w construction (unordered offsets)            (stream B)
//   x_new = xv * (1 + segsum_v(wv[eidx]))        (gather-reduce, fused)
//   s     = segsum_e(x_new[vidx])                (gather-reduce)
//   w_new = we * (1 + s@Wx2^T + deg_w*bx2)       (fused GEMM epilogue)
// Output: [w_new (N_W*128) | x_new (N_X*128)]  float32
// ---------------------------------------------------------------------------

#define MAX_NX 100000
#define MAX_NW 25000
#define MAX_E  800000
#define D 128

__device__ float g_xv [MAX_NX * D];
__device__ float g_wv [MAX_NW * D];
__device__ float g_we [MAX_NW * D];
__device__ float g_s  [MAX_NW * D];

// counts for x segments [0,NX), w segments [NX, NX+NW), counters at fixed tail
__device__ int g_cnt [MAX_NX + MAX_NW + 2];
__device__ int g_beg [MAX_NX + MAX_NW];
__device__ int g_cur [MAX_NX + MAX_NW];
__device__ int g_srcx[MAX_E];
__device__ int g_srcw[MAX_E];

// packed f32x2 FMA (2x fp32 FMA throughput; only reachable via PTX)
__device__ __forceinline__ float2 ffma2(float2 a, float2 b, float2 c) {
    unsigned long long au, bu, cu, du;
    memcpy(&au, &a, 8); memcpy(&bu, &b, 8); memcpy(&cu, &c, 8);
    asm("fma.rn.f32x2 %0, %1, %2, %3;" : "=l"(du) : "l"(au), "l"(bu), "l"(cu));
    float2 d; memcpy(&d, &du, 8);
    return d;
}

// ---------------------------------------------------------------------------
// GEMM: v[M,128] = A[M,128] @ W^T + bias*deg   (deg=1 if null)
//   out = mulSrc ? mulSrc*(1+v) : v
// ---------------------------------------------------------------------------
extern __shared__ float smem_dyn[];

__global__ void __launch_bounds__(256, 1)
gemm128_kernel(const float* __restrict__ A, const float* __restrict__ W,
               const float* __restrict__ bias, float* __restrict__ C, int M,
               const int* __restrict__ deg, const float* __restrict__ mulSrc)
{
    float* Ast = smem_dyn;             // [k][row]
    float* Wt  = smem_dyn + 128 * 128; // [k][col]

    const int t  = threadIdx.x;
    const int tx = t & 15;
    const int ty = t >> 4;
    const int rowBase = blockIdx.x * 128;

    {
        const int r  = t >> 1;
        const int kh = (t & 1) * 64;
        const int grow = rowBase + r;
        const bool valid = grow < M;
        const float4* Ag = (const float4*)(A + (size_t)grow * D + kh);
        const float4* Wg = (const float4*)(W + (size_t)r * D + kh);
        #pragma unroll
        for (int q = 0; q < 16; q++) {
            float4 va = valid ? Ag[q] : make_float4(0.f, 0.f, 0.f, 0.f);
            int k0 = kh + q * 4;
            Ast[(k0 + 0) * 128 + r] = va.x;
            Ast[(k0 + 1) * 128 + r] = va.y;
            Ast[(k0 + 2) * 128 + r] = va.z;
            Ast[(k0 + 3) * 128 + r] = va.w;
            float4 vw = Wg[q];
            Wt[(k0 + 0) * 128 + r] = vw.x;
            Wt[(k0 + 1) * 128 + r] = vw.y;
            Wt[(k0 + 2) * 128 + r] = vw.z;
            Wt[(k0 + 3) * 128 + r] = vw.w;
        }
    }
    __syncthreads();

    float2 acc[4][8];
    #pragma unroll
    for (int i = 0; i < 4; i++)
        #pragma unroll
        for (int p = 0; p < 8; p++) acc[i][p] = make_float2(0.f, 0.f);

    #pragma unroll 4
    for (int k = 0; k < 128; k++) {
        float2 a2[4];
        #pragma unroll
        for (int i = 0; i < 4; i++)
            a2[i] = *(const float2*)&Ast[k * 128 + ty * 8 + 2 * i];
        #pragma unroll
        for (int p = 0; p < 8; p++) {
            float wv_ = Wt[k * 128 + tx + 16 * p];
            float2 w2 = make_float2(wv_, wv_);
            #pragma unroll
            for (int i = 0; i < 4; i++)
                acc[i][p] = ffma2(a2[i], w2, acc[i][p]);
        }
    }

    float b[8];
    #pragma unroll
    for (int p = 0; p < 8; p++) b[p] = bias[tx + 16 * p];

    const bool hasMul = (mulSrc != nullptr);

    #pragma unroll
    for (int i = 0; i < 4; i++) {
        int r0 = rowBase + ty * 8 + 2 * i;
        float d0 = 1.f, d1 = 1.f;
        if (deg != nullptr) {
            if (r0 < M)     d0 = (float)deg[r0];
            if (r0 + 1 < M) d1 = (float)deg[r0 + 1];
        }
        #pragma unroll
        for (int p = 0; p < 8; p++) {
            int col = tx + 16 * p;
            if (r0 < M) {
                float v = acc[i][p].x + b[p] * d0;
                if (hasMul) { float m = mulSrc[(size_t)r0 * D + col]; v = fmaf(m, v, m); }
                C[(size_t)r0 * D + col] = v;
            }
            if (r0 + 1 < M) {
                float v = acc[i][p].y + b[p] * d1;
                if (hasMul) { float m = mulSrc[(size_t)(r0 + 1) * D + col]; v = fmaf(m, v, m); }
                C[(size_t)(r0 + 1) * D + col] = v;
            }
        }
    }
}

// ---------------------------------------------------------------------------
// CSR build
// ---------------------------------------------------------------------------
__global__ void hist_kernel(const int* __restrict__ vidx, const int* __restrict__ eidx,
                            int* __restrict__ cnt, int nx, int E)
{
    int e = blockIdx.x * blockDim.x + threadIdx.x;
    if (e < E) {
        atomicAdd(&cnt[vidx[e]], 1);
        atomicAdd(&cnt[nx + eidx[e]], 1);
    }
}

// one kernel: per-block scan + atomic base grab (unordered segment placement)
__global__ void __launch_bounds__(1024)
offsets_kernel(const int* __restrict__ cnt, int* __restrict__ beg,
               int* __restrict__ cur, int* __restrict__ ctr,
               int nx, int nw, int nbx)
{
    const int isW = (blockIdx.x >= nbx) ? 1 : 0;
    const int blk = isW ? (blockIdx.x - nbx) : blockIdx.x;
    const int n   = isW ? nw : nx;
    const int off = isW ? nx : 0;

    const int t = threadIdx.x;
    const int i = blk * 1024 + t;
    int v = (i < n) ? cnt[off + i] : 0;

    const int lane = t & 31, wid = t >> 5;
    int s = v;
    #pragma unroll
    for (int o = 1; o < 32; o <<= 1) {
        int u = __shfl_up_sync(0xffffffffu, s, o);
        if (lane >= o) s += u;
    }
    __shared__ int wsum[32];
    __shared__ int base;
    if (lane == 31) wsum[wid] = s;
    __syncthreads();
    if (wid == 0) {
        int ws = wsum[lane];
        #pragma unroll
        for (int o = 1; o < 32; o <<= 1) {
            int u = __shfl_up_sync(0xffffffffu, ws, o);
            if (lane >= o) ws += u;
        }
        wsum[lane] = ws;
        if (lane == 31) base = atomicAdd(&ctr[isW], ws);
    }
    __syncthreads();
    int excl = base + s - v + (wid > 0 ? wsum[wid - 1] : 0);
    if (i < n) { beg[off + i] = excl; cur[off + i] = excl; }
}

__global__ void place_kernel(const int* __restrict__ vidx, const int* __restrict__ eidx,
                             int* __restrict__ cur, int* __restrict__ srcx,
                             int* __restrict__ srcw, int nx, int E)
{
    int e = blockIdx.x * blockDim.x + threadIdx.x;
    if (e < E) {
        int v = vidx[e], hw = eidx[e];
        int p1 = atomicAdd(&cur[v], 1);
        srcx[p1] = hw;
        int p2 = atomicAdd(&cur[nx + hw], 1);
        srcw[p2] = v;
    }
}

// ---------------------------------------------------------------------------
// Segment gather-reduce: warp per segment; lane = float4 chunk.
//   acc = sum_{k in [beg, beg+cnt)} src[lst[k]]
//   out = lin ? lin*(1+acc) : acc
// ---------------------------------------------------------------------------
__global__ void seg_reduce_kernel(const int* __restrict__ beg, const int* __restrict__ cnt,
                                  const int* __restrict__ lst,
                                  const float* __restrict__ src, const float* __restrict__ lin,
                                  float* __restrict__ out, int N)
{
    const int seg  = (blockIdx.x * blockDim.x + threadIdx.x) >> 5;
    const int lane = threadIdx.x & 31;
    if (seg >= N) return;
    int k = beg[seg];
    const int end = k + cnt[seg];
    float4 acc = make_float4(0.f, 0.f, 0.f, 0.f);
    for (; k + 3 < end; k += 4) {
        int s0 = __ldg(&lst[k]);
        int s1 = __ldg(&lst[k + 1]);
        int s2 = __ldg(&lst[k + 2]);
        int s3 = __ldg(&lst[k + 3]);
        float4 v0 = *(const float4*)(src + (size_t)s0 * D + lane * 4);
        float4 v1 = *(const float4*)(src + (size_t)s1 * D + lane * 4);
        float4 v2 = *(const float4*)(src + (size_t)s2 * D + lane * 4);
        float4 v3 = *(const float4*)(src + (size_t)s3 * D + lane * 4);
        acc.x += (v0.x + v1.x) + (v2.x + v3.x);
        acc.y += (v0.y + v1.y) + (v2.y + v3.y);
        acc.z += (v0.z + v1.z) + (v2.z + v3.z);
        acc.w += (v0.w + v1.w) + (v2.w + v3.w);
    }
    for (; k < end; k++) {
        int s0 = __ldg(&lst[k]);
        float4 v0 = *(const float4*)(src + (size_t)s0 * D + lane * 4);
        acc.x += v0.x; acc.y += v0.y; acc.z += v0.z; acc.w += v0.w;
    }
    float4 o;
    if (lin != nullptr) {
        float4 l = *(const float4*)(lin + (size_t)seg * D + lane * 4);
        o.x = fmaf(acc.x, l.x, l.x);
        o.y = fmaf(acc.y, l.y, l.y);
        o.z = fmaf(acc.z, l.z, l.z);
        o.w = fmaf(acc.w, l.w, l.w);
    } else {
        o = acc;
    }
    *(float4*)(out + (size_t)seg * D + lane * 4) = o;
}

extern "C" void kernel_launch(void* const* d_in, const int* in_sizes, int n_in,
                              void* d_out, int out_size)
{
    const float* x   = (const float*)d_in[0];
    const float* w   = (const float*)d_in[1];
    const float* Wx1 = (const float*)d_in[2];
    const float* bx1 = (const float*)d_in[3];
    const float* Ww1 = (const float*)d_in[4];
    const float* bw1 = (const float*)d_in[5];
    const float* Wx2 = (const float*)d_in[6];
    const float* bx2 = (const float*)d_in[7];
    const float* Ww2 = (const float*)d_in[8];
    const float* bw2 = (const float*)d_in[9];
    const int*   h   = (const int*)d_in[10];

    const int N_X = in_sizes[0] / D;
    const int N_W = in_sizes[1] / D;
    const int E   = in_sizes[10] / 2;
    const int* vidx = h;
    const int* eidx = h + E;

    float* out_w = (float*)d_out;
    float* out_x = (float*)d_out + (size_t)N_W * D;

    float *p_xv, *p_wv, *p_we, *p_s;
    int *p_cnt, *p_beg, *p_cur, *p_srcx, *p_srcw;
    cudaGetSymbolAddress((void**)&p_xv,   g_xv);
    cudaGetSymbolAddress((void**)&p_wv,   g_wv);
    cudaGetSymbolAddress((void**)&p_we,   g_we);
    cudaGetSymbolAddress((void**)&p_s,    g_s);
    cudaGetSymbolAddress((void**)&p_cnt,  g_cnt);
    cudaGetSymbolAddress((void**)&p_beg,  g_beg);
    cudaGetSymbolAddress((void**)&p_cur,  g_cur);
    cudaGetSymbolAddress((void**)&p_srcx, g_srcx);
    cudaGetSymbolAddress((void**)&p_srcw, g_srcw);
    int* p_ctr = p_cnt + MAX_NX + MAX_NW;   // 2 counters at fixed tail

    const int SMEM = 2 * 128 * 128 * (int)sizeof(float); // 128 KB
    cudaFuncSetAttribute(gemm128_kernel,
                         cudaFuncAttributeMaxDynamicSharedMemorySize, SMEM);

    // streams/events for fork-join inside capture (created once; host-side only)
    static cudaStream_t sA = nullptr, sB = nullptr;
    static cudaEvent_t e0 = nullptr, eA = nullptr, eA2 = nullptr, eB = nullptr;
    if (sA == nullptr) {
        cudaStreamCreateWithFlags(&sA, cudaStreamNonBlocking);
        cudaStreamCreateWithFlags(&sB, cudaStreamNonBlocking);
        cudaEventCreateWithFlags(&e0,  cudaEventDisableTiming);
        cudaEventCreateWithFlags(&eA,  cudaEventDisableTiming);
        cudaEventCreateWithFlags(&eA2, cudaEventDisableTiming);
        cudaEventCreateWithFlags(&eB,  cudaEventDisableTiming);
    }

    const int gx  = (N_X + 127) / 128;
    const int gw  = (N_W + 127) / 128;
    const int nbx = (N_X + 1023) / 1024;
    const int nbw = (N_W + 1023) / 1024;
    const int ge  = (E + 255) / 256;

    // fork
    cudaEventRecord(e0, 0);
    cudaStreamWaitEvent(sA, e0, 0);
    cudaStreamWaitEvent(sB, e0, 0);

    // ---- stream B: CSR construction (launches 1..4) ----
    cudaMemsetAsync(p_cnt, 0, (size_t)(MAX_NX + MAX_NW + 2) * sizeof(int), sB);
    hist_kernel<<<ge, 256, 0, sB>>>(vidx, eidx, p_cnt, N_X, E);
    offsets_kernel<<<nbx + nbw, 1024, 0, sB>>>(p_cnt, p_beg, p_cur, p_ctr, N_X, N_W, nbx);
    place_kernel<<<ge, 256, 0, sB>>>(vidx, eidx, p_cur, p_srcx, p_srcw, N_X, E);
    cudaEventRecord(eB, sB);

    // ---- stream A: graph-independent GEMMs (launches 5..7; #6 = big gx gemm) ----
    gemm128_kernel<<<gw, 256, SMEM, sA>>>(w, Ww1, bw1, p_wv, N_W, nullptr, nullptr);
    gemm128_kernel<<<gx, 256, SMEM, sA>>>(x, Wx1, bx1, p_xv, N_X, nullptr, nullptr);
    cudaEventRecord(eA, sA);
    gemm128_kernel<<<gw, 256, SMEM, sA>>>(w, Ww2, bw2, p_we, N_W, nullptr, nullptr);
    cudaEventRecord(eA2, sA);

    // join for phase 1
    cudaStreamWaitEvent(0, eA, 0);
    cudaStreamWaitEvent(0, eB, 0);

    // ---- phase 1: x_new = xv * (1 + segsum_v(wv)) ----
    seg_reduce_kernel<<<(N_X + 7) / 8, 256>>>(p_beg, p_cnt, p_srcx, p_wv, p_xv, out_x, N_X);

    // ---- phase 2: s = segsum_e(x_new); w_new = we*(1 + s@Wx2^T + deg*bx2) ----
    seg_reduce_kernel<<<(N_W + 7) / 8, 256>>>(p_beg + N_X, p_cnt + N_X, p_srcw,
                                              out_x, nullptr, p_s, N_W);
    cudaStreamWaitEvent(0, eA2, 0);
    gemm128_kernel<<<gw, 256, SMEM>>>(p_s, Wx2, bx2, out_w, N_W, p_cnt + N_X, p_we);
}